// round 10
// baseline (speedup 1.0000x reference)
#include <cuda_runtime.h>
#include <cuda_bf16.h>

// WeaveLayer permutation:
//   out[b, yb*8 + hi*4 + px, xb*8 + wi*4 + py] = in[b, yb*4 + py, xb*4 + px, q=2*hi+wi]
// in (32, 768, 768, 4) f32, out (32, 1536, 1536, 1) f32.
//
// R8: smem-free. The permutation is a 4x4 float transpose across each py-quad
// (lanes differing in bits 0-1). Each thread loads one pixel's float4 (channels
// q=0..3); after a 2-stage shfl.bfly transpose, lane r of the quad holds
// channel q=r from py=0..3 — exactly one contiguous output float4 at
// (row = yb*8 + (r>>1)*4 + px, col4 = xb*2 + (r&1)).
//
// Lane map: py = tid&3, px = (tid>>2)&3, xb_low = (tid>>4)&1.
//   Loads:  warp = 4 rows x 8 consecutive pixels = 4 full 128B lines.
//   Stores: warp = 8 rows x 64B contiguous = 16 sectors (no amplification);
//           partner warp (tid bit5) completes each 128B line.

#define B_      32
#define YB      192           // 768 / 4
#define THREADS 512

__global__ __launch_bounds__(THREADS) void weave_kernel(
    const float4* __restrict__ in4,   // (32, 768, 768) pixels, 1 float4 each
    float4* __restrict__ out4)        // (32, 1536, 384) float4
{
    const int bid = blockIdx.x;
    const int yb  = bid % YB;
    const int b   = bid / YB;
    const int tid = threadIdx.x;

    const int r = tid & 3;            // quad rank: dual role py (load) / q (store)

    const int in_base  = (b * 768  + yb * 4) * 768;
    const int out_base = (b * 1536 + yb * 8) * 384;

    #pragma unroll
    for (int k = 0; k < 6; k++) {
        const int i  = tid + k * THREADS;      // 0..3071
        const int px = (i >> 2) & 3;
        const int xb = i >> 4;                 // 0..191
        const int xl = (xb << 2) + px;         // pixel x

        // Load: lane's pixel (py = r), channels q=0..3 in v[0..3]
        const float4 p = in4[in_base + r * 768 + xl];
        float v0 = p.x, v1 = p.y, v2 = p.z, v3 = p.w;

        // ---- 4x4 transpose across the py-quad (lanes r=0..3) ----
        // Stage 1: bit 0 (lane xor 1, index bit 0)
        if (r & 1) { float t = v0; v0 = v1; v1 = t;
                     t = v2; v2 = v3; v3 = t; }
        v1 = __shfl_xor_sync(0xFFFFFFFFu, v1, 1);
        v3 = __shfl_xor_sync(0xFFFFFFFFu, v3, 1);
        if (r & 1) { float t = v0; v0 = v1; v1 = t;
                     t = v2; v2 = v3; v3 = t; }
        // Stage 2: bit 1 (lane xor 2, index bit 1)
        if (r & 2) { float t = v0; v0 = v2; v2 = t;
                     t = v1; v1 = v3; v3 = t; }
        v2 = __shfl_xor_sync(0xFFFFFFFFu, v2, 2);
        v3 = __shfl_xor_sync(0xFFFFFFFFu, v3, 2);
        if (r & 2) { float t = v0; v0 = v2; v2 = t;
                     t = v1; v1 = v3; v3 = t; }
        // Now v[py] = channel q=r of pixel (py, px, xb):
        // = out[b, yb*8 + (r>>1)*4 + px, xb*8 + (r&1)*4 + py]

        const int hi = r >> 1;
        const int wi = r & 1;
        out4[out_base + (hi * 4 + px) * 384 + (xb << 1) + wi] =
            make_float4(v0, v1, v2, v3);
    }
}

extern "C" void kernel_launch(void* const* d_in, const int* in_sizes, int n_in,
                              void* d_out, int out_size) {
    const float4* in4 = (const float4*)d_in[0];
    float4* out4 = (float4*)d_out;
    weave_kernel<<<B_ * YB, THREADS>>>(in4, out4);
}